// round 1
// baseline (speedup 1.0000x reference)
#include <cuda_runtime.h>

#define NODES  50000
#define NEDGE  800000
#define AUGE   (NEDGE + NODES)     // 850000
#define INC    128
#define HIDC   64
#define NHEADS 4
#define H1DIM  (NHEADS * HIDC)     // 256

// ------------------------- scratch (static device memory) -------------------
__device__ float    g_h1lin[(size_t)NODES * H1DIM];
__device__ float    g_agg1 [(size_t)NODES * H1DIM];
__device__ float    g_h2lin[(size_t)NODES * HIDC];
__device__ float    g_agg2 [(size_t)NODES * HIDC];
__device__ float    g_ssrc1[NODES * NHEADS];
__device__ float    g_sdst1[NODES * NHEADS];
__device__ float    g_den1 [NODES * NHEADS];
__device__ unsigned g_mx1  [NODES * NHEADS];
__device__ float    g_ssrc2[NODES];
__device__ float    g_sdst2[NODES];
__device__ float    g_den2 [NODES];
__device__ unsigned g_mx2  [NODES];
__device__ int      g_ei   [2 * NEDGE];
__device__ int      g_is64;

// ------------------------- helpers ------------------------------------------
__device__ __forceinline__ unsigned fenc(float x) {
    unsigned u = __float_as_uint(x);
    return (u >> 31) ? ~u : (u | 0x80000000u);
}
__device__ __forceinline__ float fdec(unsigned e) {
    return (e >> 31) ? __uint_as_float(e ^ 0x80000000u) : __uint_as_float(~e);
}
__device__ __forceinline__ void redAdd4(float4* p, float4 v) {
    asm volatile("red.global.add.v4.f32 [%0], {%1,%2,%3,%4};"
                 :: "l"(p), "f"(v.x), "f"(v.y), "f"(v.z), "f"(v.w) : "memory");
}
__device__ __forceinline__ float lrelu(float x) { return x >= 0.f ? x : 0.2f * x; }

// ------------------------- edge index dtype detect + normalize --------------
__global__ void detect_k(const void* p) {
    __shared__ int nz;
    if (threadIdx.x == 0) nz = 0;
    __syncthreads();
    const int2* q = (const int2*)p;
    for (int i = threadIdx.x; i < 4096; i += blockDim.x)
        if (q[i].y != 0) nz = 1;          // benign race: all writers store 1
    __syncthreads();
    if (threadIdx.x == 0) g_is64 = (nz == 0) ? 1 : 0;
}

__global__ void conv_k(const void* p) {
    int i = blockIdx.x * blockDim.x + threadIdx.x;
    if (i >= 2 * NEDGE) return;
    long long v = g_is64 ? ((const long long*)p)[i]
                         : (long long)((const int*)p)[i];
    g_ei[i] = (int)v;
}

// ------------------------- tiled fp32 GEMM (64x64 tile, 4x4/thread) ---------
__global__ void __launch_bounds__(256) gemm64_k(
    const float* __restrict__ A, const float* __restrict__ B,
    float* __restrict__ C, int M, int K, int Nc)
{
    __shared__ float As[64][68];
    __shared__ float Bs[64][68];
    int t = threadIdx.x;
    int m0 = blockIdx.x * 64, n0 = blockIdx.y * 64;
    int tr = t >> 4, tc = t & 15;
    float acc[4][4] = {};
    for (int kt = 0; kt < K; kt += 64) {
        #pragma unroll
        for (int i = t; i < 1024; i += 256) {
            int r = i >> 4, c4 = (i & 15) << 2;
            int gr = m0 + r;
            float4 v = make_float4(0.f, 0.f, 0.f, 0.f);
            if (gr < M) v = *(const float4*)(A + (long)gr * K + kt + c4);
            *(float4*)&As[r][c4] = v;
        }
        #pragma unroll
        for (int i = t; i < 1024; i += 256) {
            int r = i >> 4, c4 = (i & 15) << 2;
            *(float4*)&Bs[r][c4] = *(const float4*)(B + (long)(kt + r) * Nc + n0 + c4);
        }
        __syncthreads();
        #pragma unroll
        for (int k4 = 0; k4 < 16; k4++) {
            float4 a4[4], b4[4];
            #pragma unroll
            for (int j = 0; j < 4; j++) a4[j] = *(const float4*)&As[tr * 4 + j][k4 * 4];
            #pragma unroll
            for (int kk = 0; kk < 4; kk++) b4[kk] = *(const float4*)&Bs[k4 * 4 + kk][tc * 4];
            #pragma unroll
            for (int j = 0; j < 4; j++) {
                float ax = a4[j].x, ay = a4[j].y, az = a4[j].z, aw = a4[j].w;
                acc[j][0] += ax * b4[0].x + ay * b4[1].x + az * b4[2].x + aw * b4[3].x;
                acc[j][1] += ax * b4[0].y + ay * b4[1].y + az * b4[2].y + aw * b4[3].y;
                acc[j][2] += ax * b4[0].z + ay * b4[1].z + az * b4[2].z + aw * b4[3].z;
                acc[j][3] += ax * b4[0].w + ay * b4[1].w + az * b4[2].w + aw * b4[3].w;
            }
        }
        __syncthreads();
    }
    #pragma unroll
    for (int j = 0; j < 4; j++) {
        int gr = m0 + tr * 4 + j;
        if (gr < M) {
            float4 v = make_float4(acc[j][0], acc[j][1], acc[j][2], acc[j][3]);
            *(float4*)(C + (long)gr * Nc + n0 + tc * 4) = v;
        }
    }
}

// ------------------------- attention scores (one warp per node-head) --------
__global__ void scores_k(const float* __restrict__ h,
                         const float* __restrict__ asrc,
                         const float* __restrict__ adst,
                         float* __restrict__ ssrc, float* __restrict__ sdst,
                         int NH, int H)
{
    int w = (int)(((long)blockIdx.x * blockDim.x + threadIdx.x) >> 5);
    int lane = threadIdx.x & 31;
    if (w >= NH) return;
    int hh = w % H;
    const float* row = h + (long)w * 64;
    float v1 = row[lane], v2 = row[lane + 32];
    float ss = v1 * asrc[hh * 64 + lane] + v2 * asrc[hh * 64 + lane + 32];
    float sd = v1 * adst[hh * 64 + lane] + v2 * adst[hh * 64 + lane + 32];
    #pragma unroll
    for (int o = 16; o; o >>= 1) {
        ss += __shfl_xor_sync(0xffffffffu, ss, o);
        sd += __shfl_xor_sync(0xffffffffu, sd, o);
    }
    if (lane == 0) { ssrc[w] = ss; sdst[w] = sd; }
}

// ------------------------- init buffers -------------------------------------
__global__ void init1_k() {
    long i = (long)blockIdx.x * blockDim.x + threadIdx.x;
    if (i < NODES * NHEADS) { g_mx1[i] = 0u; g_den1[i] = 0.f; }
    if (i < (long)NODES * H1DIM) g_agg1[i] = 0.f;
}
__global__ void init2_k() {
    long i = (long)blockIdx.x * blockDim.x + threadIdx.x;
    if (i < NODES) { g_mx2[i] = 0u; g_den2[i] = 0.f; }
    if (i < (long)NODES * HIDC) g_agg2[i] = 0.f;
}

// ------------------------- segment max / denom ------------------------------
__global__ void emax_k(const float* __restrict__ ssrc, const float* __restrict__ sdst,
                       unsigned* __restrict__ mx, int H)
{
    long idx = (long)blockIdx.x * blockDim.x + threadIdx.x;
    if (idx >= (long)AUGE * H) return;
    int i = (int)(idx / H), hh = (int)(idx - (long)i * H);
    int s, d;
    if (i < NEDGE) { s = g_ei[i]; d = g_ei[NEDGE + i]; } else { s = d = i - NEDGE; }
    float e = lrelu(ssrc[s * H + hh] + sdst[d * H + hh]);
    atomicMax(&mx[d * H + hh], fenc(e));
}

__global__ void eden_k(const float* __restrict__ ssrc, const float* __restrict__ sdst,
                       const unsigned* __restrict__ mx, float* __restrict__ den, int H)
{
    long idx = (long)blockIdx.x * blockDim.x + threadIdx.x;
    if (idx >= (long)AUGE * H) return;
    int i = (int)(idx / H), hh = (int)(idx - (long)i * H);
    int s, d;
    if (i < NEDGE) { s = g_ei[i]; d = g_ei[NEDGE + i]; } else { s = d = i - NEDGE; }
    float e = lrelu(ssrc[s * H + hh] + sdst[d * H + hh]);
    float m = fdec(mx[d * H + hh]);
    atomicAdd(&den[d * H + hh], expf(e - m));
}

// ------------------------- weighted aggregation (vectorized reds) -----------
__global__ void eagg1_k() {
    long tid = (long)blockIdx.x * blockDim.x + threadIdx.x;
    int w = (int)(tid >> 5);
    if (w >= AUGE) return;
    int lane = threadIdx.x & 31;
    int s, d;
    if (w < NEDGE) { s = g_ei[w]; d = g_ei[NEDGE + w]; } else { s = d = w - NEDGE; }
    float alpha[NHEADS];
    #pragma unroll
    for (int hh = 0; hh < NHEADS; hh++) {
        float e = lrelu(g_ssrc1[s * 4 + hh] + g_sdst1[d * 4 + hh]);
        float m = fdec(g_mx1[d * 4 + hh]);
        alpha[hh] = expf(e - m) / (g_den1[d * 4 + hh] + 1e-16f);
    }
    const float4* hp = (const float4*)(g_h1lin + (long)s * H1DIM);
    float4*       ap = (float4*)(g_agg1  + (long)d * H1DIM);
    #pragma unroll
    for (int q = lane; q < 64; q += 32) {
        float4 v = hp[q];
        float a = alpha[q >> 4];
        redAdd4(ap + q, make_float4(v.x * a, v.y * a, v.z * a, v.w * a));
    }
}

__global__ void eagg2_k() {
    long tid = (long)blockIdx.x * blockDim.x + threadIdx.x;
    int w = (int)(tid >> 4);
    if (w >= AUGE) return;
    int q = (int)(tid & 15);
    int s, d;
    if (w < NEDGE) { s = g_ei[w]; d = g_ei[NEDGE + w]; } else { s = d = w - NEDGE; }
    float e = lrelu(g_ssrc2[s] + g_sdst2[d]);
    float alpha = expf(e - fdec(g_mx2[d])) / (g_den2[d] + 1e-16f);
    float4 v = ((const float4*)(g_h2lin + (long)s * HIDC))[q];
    redAdd4((float4*)(g_agg2 + (long)d * HIDC) + q,
            make_float4(v.x * alpha, v.y * alpha, v.z * alpha, v.w * alpha));
}

// ------------------------- bias (+relu) epilogue ----------------------------
__global__ void epi_k(float* __restrict__ p, const float* __restrict__ b,
                      long n, int C, int dorelu)
{
    long i = (long)blockIdx.x * blockDim.x + threadIdx.x;
    if (i >= n) return;
    float v = p[i] + b[(int)(i % C)];
    p[i] = dorelu ? fmaxf(v, 0.f) : v;
}

// ------------------------- edge MLP: gather-GEMM [E,128]x[128,64] -> [E,2] --
__global__ void __launch_bounds__(256) mlp_k(
    const float* __restrict__ h2,
    const float* __restrict__ Wm1, const float* __restrict__ bm1,
    const float* __restrict__ Wm2, const float* __restrict__ bm2,
    float* __restrict__ out)
{
    __shared__ float Efs[64][68];
    __shared__ float Ws[64][68];
    __shared__ int es[64], ed[64];
    int t = threadIdx.x;
    int e0 = blockIdx.x * 64;                       // E divisible by 64
    if (t < 64)        es[t]      = g_ei[e0 + t];
    else if (t < 128)  ed[t - 64] = g_ei[NEDGE + e0 + (t - 64)];
    __syncthreads();

    int tr = t >> 4, tc = t & 15;
    float acc[4][4] = {};
    for (int kt = 0; kt < 128; kt += 64) {
        #pragma unroll
        for (int i = t; i < 1024; i += 256) {
            int r = i >> 4, c4 = (i & 15) << 2;
            int node = (kt == 0) ? es[r] : ed[r];
            *(float4*)&Efs[r][c4] = *(const float4*)(h2 + (long)node * 64 + c4);
        }
        #pragma unroll
        for (int i = t; i < 1024; i += 256) {
            int r = i >> 4, c4 = (i & 15) << 2;
            *(float4*)&Ws[r][c4] = *(const float4*)(Wm1 + (long)(kt + r) * 64 + c4);
        }
        __syncthreads();
        #pragma unroll
        for (int k4 = 0; k4 < 16; k4++) {
            float4 a4[4], b4[4];
            #pragma unroll
            for (int j = 0; j < 4; j++) a4[j] = *(const float4*)&Efs[tr * 4 + j][k4 * 4];
            #pragma unroll
            for (int kk = 0; kk < 4; kk++) b4[kk] = *(const float4*)&Ws[k4 * 4 + kk][tc * 4];
            #pragma unroll
            for (int j = 0; j < 4; j++) {
                float ax = a4[j].x, ay = a4[j].y, az = a4[j].z, aw = a4[j].w;
                acc[j][0] += ax * b4[0].x + ay * b4[1].x + az * b4[2].x + aw * b4[3].x;
                acc[j][1] += ax * b4[0].y + ay * b4[1].y + az * b4[2].y + aw * b4[3].y;
                acc[j][2] += ax * b4[0].z + ay * b4[1].z + az * b4[2].z + aw * b4[3].z;
                acc[j][3] += ax * b4[0].w + ay * b4[1].w + az * b4[2].w + aw * b4[3].w;
            }
        }
        __syncthreads();
    }
    // relu + second projection [64]->[2], reduce across the 16 tc-threads
    float w2l[8];
    #pragma unroll
    for (int c = 0; c < 4; c++) {
        int gc = tc * 4 + c;
        w2l[c * 2 + 0] = Wm2[gc * 2 + 0];
        w2l[c * 2 + 1] = Wm2[gc * 2 + 1];
    }
    #pragma unroll
    for (int j = 0; j < 4; j++) {
        float o0 = 0.f, o1 = 0.f;
        #pragma unroll
        for (int c = 0; c < 4; c++) {
            int gc = tc * 4 + c;
            float hv = fmaxf(acc[j][c] + bm1[gc], 0.f);
            o0 += hv * w2l[c * 2 + 0];
            o1 += hv * w2l[c * 2 + 1];
        }
        #pragma unroll
        for (int off = 8; off; off >>= 1) {
            o0 += __shfl_xor_sync(0xffffffffu, o0, off);
            o1 += __shfl_xor_sync(0xffffffffu, o1, off);
        }
        if (tc == 0) {
            long e = e0 + tr * 4 + j;
            out[e * 2 + 0] = o0 + bm2[0];
            out[e * 2 + 1] = o1 + bm2[1];
        }
    }
}

// ------------------------- launch -------------------------------------------
extern "C" void kernel_launch(void* const* d_in, const int* in_sizes, int n_in,
                              void* d_out, int out_size)
{
    const float* x   = (const float*)d_in[0];
    const void*  eir = d_in[1];
    const float* W1  = (const float*)d_in[2];
    const float* as1 = (const float*)d_in[3];
    const float* ad1 = (const float*)d_in[4];
    const float* b1  = (const float*)d_in[5];
    const float* W2  = (const float*)d_in[6];
    const float* as2 = (const float*)d_in[7];
    const float* ad2 = (const float*)d_in[8];
    const float* b2  = (const float*)d_in[9];
    const float* Wm1 = (const float*)d_in[10];
    const float* bm1 = (const float*)d_in[11];
    const float* Wm2 = (const float*)d_in[12];
    const float* bm2 = (const float*)d_in[13];
    float* out = (float*)d_out;

    void* p;
    cudaGetSymbolAddress(&p, g_h1lin); float* h1lin = (float*)p;
    cudaGetSymbolAddress(&p, g_agg1);  float* agg1  = (float*)p;
    cudaGetSymbolAddress(&p, g_h2lin); float* h2lin = (float*)p;
    cudaGetSymbolAddress(&p, g_agg2);  float* agg2  = (float*)p;
    cudaGetSymbolAddress(&p, g_ssrc1); float* ssrc1 = (float*)p;
    cudaGetSymbolAddress(&p, g_sdst1); float* sdst1 = (float*)p;
    cudaGetSymbolAddress(&p, g_den1);  float* den1  = (float*)p;
    cudaGetSymbolAddress(&p, g_mx1);   unsigned* mx1 = (unsigned*)p;
    cudaGetSymbolAddress(&p, g_ssrc2); float* ssrc2 = (float*)p;
    cudaGetSymbolAddress(&p, g_sdst2); float* sdst2 = (float*)p;
    cudaGetSymbolAddress(&p, g_den2);  float* den2  = (float*)p;
    cudaGetSymbolAddress(&p, g_mx2);   unsigned* mx2 = (unsigned*)p;

    // normalize edge index to int32 (handles both int32 and int64 inputs)
    detect_k<<<1, 256>>>(eir);
    conv_k<<<(2 * NEDGE + 255) / 256, 256>>>(eir);

    // ---- layer 1 (4 heads, concat, relu) ----
    gemm64_k<<<dim3((NODES + 63) / 64, H1DIM / 64), 256>>>(x, W1, h1lin, NODES, INC, H1DIM);
    scores_k<<<(NODES * NHEADS * 32 + 255) / 256, 256>>>(h1lin, as1, ad1, ssrc1, sdst1,
                                                         NODES * NHEADS, NHEADS);
    init1_k<<<(int)(((long)NODES * H1DIM + 255) / 256), 256>>>();
    emax_k<<<(int)(((long)AUGE * NHEADS + 255) / 256), 256>>>(ssrc1, sdst1, mx1, NHEADS);
    eden_k<<<(int)(((long)AUGE * NHEADS + 255) / 256), 256>>>(ssrc1, sdst1, mx1, den1, NHEADS);
    eagg1_k<<<(int)(((long)AUGE * 32 + 255) / 256), 256>>>();
    epi_k<<<(int)(((long)NODES * H1DIM + 255) / 256), 256>>>(agg1, b1,
                                                             (long)NODES * H1DIM, H1DIM, 1);

    // ---- layer 2 (1 head, mean == identity, +bias) ----
    gemm64_k<<<dim3((NODES + 63) / 64, 1), 256>>>(agg1, W2, h2lin, NODES, H1DIM, HIDC);
    scores_k<<<(NODES * 32 + 255) / 256, 256>>>(h2lin, as2, ad2, ssrc2, sdst2, NODES, 1);
    init2_k<<<(int)(((long)NODES * HIDC + 255) / 256), 256>>>();
    emax_k<<<(AUGE + 255) / 256, 256>>>(ssrc2, sdst2, mx2, 1);
    eden_k<<<(AUGE + 255) / 256, 256>>>(ssrc2, sdst2, mx2, den2, 1);
    eagg2_k<<<(int)(((long)AUGE * 16 + 255) / 256), 256>>>();
    epi_k<<<(int)(((long)NODES * HIDC + 255) / 256), 256>>>(agg2, b2,
                                                            (long)NODES * HIDC, HIDC, 0);

    // ---- edge MLP ----
    mlp_k<<<NEDGE / 64, 256>>>(agg2, Wm1, bm1, Wm2, bm2, out);
}

// round 2
// speedup vs baseline: 1.5082x; 1.5082x over previous
#include <cuda_runtime.h>

#define NODES  50000
#define NEDGE  800000
#define AUGE   (NEDGE + NODES)     // 850000
#define INC    128
#define HIDC   64
#define NHEADS 4
#define H1DIM  (NHEADS * HIDC)     // 256

// ------------------------- scratch (static device memory) -------------------
__device__ float    g_h1lin[(size_t)NODES * H1DIM];
__device__ float    g_agg1 [(size_t)NODES * H1DIM];
__device__ float    g_h2lin[(size_t)NODES * HIDC];
__device__ float    g_agg2 [(size_t)NODES * HIDC];
__device__ float    g_PQ   [(size_t)NODES * 2 * HIDC];   // P|Q per node
__device__ float    g_Bc   [HIDC * 2 * HIDC];            // repacked Wm1
__device__ float    g_ssrc1[NODES * NHEADS];
__device__ float    g_sdst1[NODES * NHEADS];
__device__ float    g_den1 [NODES * NHEADS];
__device__ float    g_ex1  [(size_t)AUGE * NHEADS];
__device__ float    g_ssrc2[NODES];
__device__ float    g_sdst2[NODES];
__device__ float    g_den2 [NODES];
__device__ float    g_ex2  [AUGE];
__device__ int      g_ei   [2 * NEDGE];
__device__ int      g_is64;

// ------------------------- helpers ------------------------------------------
__device__ __forceinline__ void redAdd4(float4* p, float4 v) {
    asm volatile("red.global.add.v4.f32 [%0], {%1,%2,%3,%4};"
                 :: "l"(p), "f"(v.x), "f"(v.y), "f"(v.z), "f"(v.w) : "memory");
}
__device__ __forceinline__ float lrelu(float x) { return x >= 0.f ? x : 0.2f * x; }

// ------------------------- edge index dtype detect + normalize --------------
__global__ void detect_k(const void* p) {
    __shared__ int nz;
    if (threadIdx.x == 0) nz = 0;
    __syncthreads();
    const int2* q = (const int2*)p;
    for (int i = threadIdx.x; i < 4096; i += blockDim.x)
        if (q[i].y != 0) nz = 1;
    __syncthreads();
    if (threadIdx.x == 0) g_is64 = (nz == 0) ? 1 : 0;
}
__global__ void conv_k(const void* p) {
    int i = blockIdx.x * blockDim.x + threadIdx.x;
    if (i >= 2 * NEDGE) return;
    long long v = g_is64 ? ((const long long*)p)[i]
                         : (long long)((const int*)p)[i];
    g_ei[i] = (int)v;
}

// ------------------------- tiled fp32 GEMM (64x64 tile, 4x4/thread) ---------
// AMODE: 0 = plain A, 1 = relu(A + biasA[k]), 2 = A + biasA[k]
template<int AMODE>
__global__ void __launch_bounds__(256) gemm64_k(
    const float* __restrict__ A, const float* __restrict__ B,
    const float* __restrict__ biasA,
    float* __restrict__ C, int M, int K, int Nc)
{
    __shared__ float As[64][68];
    __shared__ float Bs[64][68];
    int t = threadIdx.x;
    int m0 = blockIdx.x * 64, n0 = blockIdx.y * 64;
    int tr = t >> 4, tc = t & 15;
    float acc[4][4] = {};
    for (int kt = 0; kt < K; kt += 64) {
        #pragma unroll
        for (int i = t; i < 1024; i += 256) {
            int r = i >> 4, c4 = (i & 15) << 2;
            int gr = m0 + r;
            float4 v = make_float4(0.f, 0.f, 0.f, 0.f);
            if (gr < M) v = *(const float4*)(A + (long)gr * K + kt + c4);
            if (AMODE) {
                float4 b = *(const float4*)(biasA + kt + c4);
                v.x += b.x; v.y += b.y; v.z += b.z; v.w += b.w;
                if (AMODE == 1) {
                    v.x = fmaxf(v.x, 0.f); v.y = fmaxf(v.y, 0.f);
                    v.z = fmaxf(v.z, 0.f); v.w = fmaxf(v.w, 0.f);
                }
            }
            *(float4*)&As[r][c4] = v;
        }
        #pragma unroll
        for (int i = t; i < 1024; i += 256) {
            int r = i >> 4, c4 = (i & 15) << 2;
            *(float4*)&Bs[r][c4] = *(const float4*)(B + (long)(kt + r) * Nc + n0 + c4);
        }
        __syncthreads();
        #pragma unroll
        for (int k4 = 0; k4 < 16; k4++) {
            float4 a4[4], b4[4];
            #pragma unroll
            for (int j = 0; j < 4; j++) a4[j] = *(const float4*)&As[tr * 4 + j][k4 * 4];
            #pragma unroll
            for (int kk = 0; kk < 4; kk++) b4[kk] = *(const float4*)&Bs[k4 * 4 + kk][tc * 4];
            #pragma unroll
            for (int j = 0; j < 4; j++) {
                float ax = a4[j].x, ay = a4[j].y, az = a4[j].z, aw = a4[j].w;
                acc[j][0] += ax * b4[0].x + ay * b4[1].x + az * b4[2].x + aw * b4[3].x;
                acc[j][1] += ax * b4[0].y + ay * b4[1].y + az * b4[2].y + aw * b4[3].y;
                acc[j][2] += ax * b4[0].z + ay * b4[1].z + az * b4[2].z + aw * b4[3].z;
                acc[j][3] += ax * b4[0].w + ay * b4[1].w + az * b4[2].w + aw * b4[3].w;
            }
        }
        __syncthreads();
    }
    #pragma unroll
    for (int j = 0; j < 4; j++) {
        int gr = m0 + tr * 4 + j;
        if (gr < M) {
            float4 v = make_float4(acc[j][0], acc[j][1], acc[j][2], acc[j][3]);
            *(float4*)(C + (long)gr * Nc + n0 + tc * 4) = v;
        }
    }
}

// ------------------------- attention scores (one warp per node-head) --------
__global__ void scores_k(const float* __restrict__ h,
                         const float* __restrict__ asrc,
                         const float* __restrict__ adst,
                         float* __restrict__ ssrc, float* __restrict__ sdst,
                         int NH, int H)
{
    int w = (int)(((long)blockIdx.x * blockDim.x + threadIdx.x) >> 5);
    int lane = threadIdx.x & 31;
    if (w >= NH) return;
    int hh = w % H;
    const float* row = h + (long)w * 64;
    float v1 = row[lane], v2 = row[lane + 32];
    float ss = v1 * asrc[hh * 64 + lane] + v2 * asrc[hh * 64 + lane + 32];
    float sd = v1 * adst[hh * 64 + lane] + v2 * adst[hh * 64 + lane + 32];
    #pragma unroll
    for (int o = 16; o; o >>= 1) {
        ss += __shfl_xor_sync(0xffffffffu, ss, o);
        sd += __shfl_xor_sync(0xffffffffu, sd, o);
    }
    if (lane == 0) { ssrc[w] = ss; sdst[w] = sd; }
}

// ------------------------- init buffers -------------------------------------
__global__ void init1_k() {
    long i = (long)blockIdx.x * blockDim.x + threadIdx.x;
    if (i < NODES * NHEADS) g_den1[i] = 0.f;
    if (i < (long)NODES * H1DIM) g_agg1[i] = 0.f;
}
__global__ void init2_k() {
    long i = (long)blockIdx.x * blockDim.x + threadIdx.x;
    if (i < NODES) g_den2[i] = 0.f;
    if (i < (long)NODES * HIDC) g_agg2[i] = 0.f;
}

// ------------------------- denom pass (no max: fp32 range is ample) ---------
__global__ void eden4_k() {
    long idx = (long)blockIdx.x * blockDim.x + threadIdx.x;
    if (idx >= (long)AUGE * 4) return;
    int i = (int)(idx >> 2), hh = (int)(idx & 3);
    int s, d;
    if (i < NEDGE) { s = g_ei[i]; d = g_ei[NEDGE + i]; } else { s = d = i - NEDGE; }
    float e = lrelu(g_ssrc1[s * 4 + hh] + g_sdst1[d * 4 + hh]);
    float ex = __expf(e);
    g_ex1[idx] = ex;
    atomicAdd(&g_den1[d * 4 + hh], ex);
}
__global__ void eden1_k() {
    int i = blockIdx.x * blockDim.x + threadIdx.x;
    if (i >= AUGE) return;
    int s, d;
    if (i < NEDGE) { s = g_ei[i]; d = g_ei[NEDGE + i]; } else { s = d = i - NEDGE; }
    float e = lrelu(g_ssrc2[s] + g_sdst2[d]);
    float ex = __expf(e);
    g_ex2[i] = ex;
    atomicAdd(&g_den2[d], ex);
}

// ------------------------- weighted aggregation (vectorized reds) -----------
__global__ void eagg1_k() {
    long tid = (long)blockIdx.x * blockDim.x + threadIdx.x;
    int w = (int)(tid >> 5);
    if (w >= AUGE) return;
    int lane = threadIdx.x & 31;
    int s, d;
    if (w < NEDGE) { s = g_ei[w]; d = g_ei[NEDGE + w]; } else { s = d = w - NEDGE; }
    float4 ex = *(const float4*)(g_ex1 + (long)w * 4);
    float4 dn = *(const float4*)(g_den1 + d * 4);
    float alpha[4];
    alpha[0] = ex.x / (dn.x + 1e-16f);
    alpha[1] = ex.y / (dn.y + 1e-16f);
    alpha[2] = ex.z / (dn.z + 1e-16f);
    alpha[3] = ex.w / (dn.w + 1e-16f);
    const float4* hp = (const float4*)(g_h1lin + (long)s * H1DIM);
    float4*       ap = (float4*)(g_agg1  + (long)d * H1DIM);
    #pragma unroll
    for (int q = lane; q < 64; q += 32) {
        float4 v = hp[q];
        float a = alpha[q >> 4];
        redAdd4(ap + q, make_float4(v.x * a, v.y * a, v.z * a, v.w * a));
    }
}
__global__ void eagg2_k() {
    long tid = (long)blockIdx.x * blockDim.x + threadIdx.x;
    int w = (int)(tid >> 4);
    if (w >= AUGE) return;
    int q = (int)(tid & 15);
    int s, d;
    if (w < NEDGE) { s = g_ei[w]; d = g_ei[NEDGE + w]; } else { s = d = w - NEDGE; }
    float alpha = g_ex2[w] / (g_den2[d] + 1e-16f);
    float4 v = ((const float4*)(g_h2lin + (long)s * HIDC))[q];
    redAdd4((float4*)(g_agg2 + (long)d * HIDC) + q,
            make_float4(v.x * alpha, v.y * alpha, v.z * alpha, v.w * alpha));
}

// ------------------------- repack Wm1 into [64 x 128] (P|Q columns) ---------
__global__ void repack_k(const float* __restrict__ Wm1) {
    int i = blockIdx.x * blockDim.x + threadIdx.x;   // 64*128
    if (i >= HIDC * 2 * HIDC) return;
    int k = i >> 7, j = i & 127;
    g_Bc[i] = (j < HIDC) ? Wm1[k * HIDC + j] : Wm1[(HIDC + k) * HIDC + (j - HIDC)];
}

// ------------------------- per-edge MLP finish: warp per edge ---------------
__global__ void __launch_bounds__(256) edge_k(
    const float* __restrict__ PQ,
    const float* __restrict__ bm1, const float* __restrict__ Wm2,
    const float* __restrict__ bm2, float* __restrict__ out)
{
    long tid = (long)blockIdx.x * blockDim.x + threadIdx.x;
    int w = (int)(tid >> 5);
    if (w >= NEDGE) return;
    int lane = threadIdx.x & 31;
    int s = g_ei[w], d = g_ei[NEDGE + w];
    float2 p = *(const float2*)(PQ + (long)s * 128 + lane * 2);          // P half
    float2 q = *(const float2*)(PQ + (long)d * 128 + 64 + lane * 2);     // Q half
    float2 b = *(const float2*)(bm1 + lane * 2);
    float h0 = fmaxf(p.x + q.x + b.x, 0.f);
    float h1 = fmaxf(p.y + q.y + b.y, 0.f);
    float4 w4 = *(const float4*)(Wm2 + lane * 4);   // rows lane*2, lane*2+1 of [64,2]
    float o0 = h0 * w4.x + h1 * w4.z;
    float o1 = h0 * w4.y + h1 * w4.w;
    #pragma unroll
    for (int off = 16; off; off >>= 1) {
        o0 += __shfl_xor_sync(0xffffffffu, o0, off);
        o1 += __shfl_xor_sync(0xffffffffu, o1, off);
    }
    if (lane == 0) {
        float2 r = make_float2(o0 + bm2[0], o1 + bm2[1]);
        *(float2*)(out + (long)w * 2) = r;
    }
}

// ------------------------- launch -------------------------------------------
extern "C" void kernel_launch(void* const* d_in, const int* in_sizes, int n_in,
                              void* d_out, int out_size)
{
    const float* x   = (const float*)d_in[0];
    const void*  eir = d_in[1];
    const float* W1  = (const float*)d_in[2];
    const float* as1 = (const float*)d_in[3];
    const float* ad1 = (const float*)d_in[4];
    const float* b1  = (const float*)d_in[5];
    const float* W2  = (const float*)d_in[6];
    const float* as2 = (const float*)d_in[7];
    const float* ad2 = (const float*)d_in[8];
    const float* b2  = (const float*)d_in[9];
    const float* Wm1 = (const float*)d_in[10];
    const float* bm1 = (const float*)d_in[11];
    const float* Wm2 = (const float*)d_in[12];
    const float* bm2 = (const float*)d_in[13];
    float* out = (float*)d_out;

    void* p;
    cudaGetSymbolAddress(&p, g_h1lin); float* h1lin = (float*)p;
    cudaGetSymbolAddress(&p, g_agg1);  float* agg1  = (float*)p;
    cudaGetSymbolAddress(&p, g_h2lin); float* h2lin = (float*)p;
    cudaGetSymbolAddress(&p, g_agg2);  float* agg2  = (float*)p;
    cudaGetSymbolAddress(&p, g_PQ);    float* PQ    = (float*)p;
    cudaGetSymbolAddress(&p, g_Bc);    float* Bc    = (float*)p;
    cudaGetSymbolAddress(&p, g_ssrc1); float* ssrc1 = (float*)p;
    cudaGetSymbolAddress(&p, g_sdst1); float* sdst1 = (float*)p;
    cudaGetSymbolAddress(&p, g_ssrc2); float* ssrc2 = (float*)p;
    cudaGetSymbolAddress(&p, g_sdst2); float* sdst2 = (float*)p;

    // normalize edge index to int32
    detect_k<<<1, 256>>>(eir);
    conv_k<<<(2 * NEDGE + 255) / 256, 256>>>(eir);

    // ---- layer 1 (4 heads, concat) ----
    gemm64_k<0><<<dim3((NODES + 63) / 64, H1DIM / 64), 256>>>(x, W1, nullptr, h1lin,
                                                              NODES, INC, H1DIM);
    scores_k<<<(NODES * NHEADS * 32 + 255) / 256, 256>>>(h1lin, as1, ad1, ssrc1, sdst1,
                                                         NODES * NHEADS, NHEADS);
    init1_k<<<(int)(((long)NODES * H1DIM + 255) / 256), 256>>>();
    eden4_k<<<(int)(((long)AUGE * 4 + 255) / 256), 256>>>();
    eagg1_k<<<(int)(((long)AUGE * 32 + 255) / 256), 256>>>();

    // ---- layer 2 (1 head); relu(agg1+b1) fused into A-load ----
    gemm64_k<1><<<dim3((NODES + 63) / 64, 1), 256>>>(agg1, W2, b1, h2lin,
                                                     NODES, H1DIM, HIDC);
    scores_k<<<(NODES * 32 + 255) / 256, 256>>>(h2lin, as2, ad2, ssrc2, sdst2, NODES, 1);
    init2_k<<<(int)(((long)NODES * HIDC + 255) / 256), 256>>>();
    eden1_k<<<(AUGE + 255) / 256, 256>>>();
    eagg2_k<<<(int)(((long)AUGE * 16 + 255) / 256), 256>>>();

    // ---- edge MLP, factorized: PQ = (agg2+b2) @ [Wm1_top | Wm1_bot] ----
    repack_k<<<(HIDC * 2 * HIDC + 255) / 256, 256>>>(Wm1);
    gemm64_k<2><<<dim3((NODES + 63) / 64, 2), 256>>>(agg2, Bc, b2, PQ,
                                                     NODES, HIDC, 2 * HIDC);
    edge_k<<<(int)(((long)NEDGE * 32 + 255) / 256), 256>>>(PQ, bm1, Wm2, bm2, out);
}